// round 14
// baseline (speedup 1.0000x reference)
#include <cuda_runtime.h>
#include <cuda_bf16.h>
#include <cstddef>
#include <cstdint>

#define B_      16
#define C_      512
#define N_      1024
#define GROUPS  32

// scratch (u32 = packed bf16x2 / f16x2)
__device__ unsigned g_xn[(size_t)B_ * 1024 * 256];   // [b*1024+t][c2]
__device__ unsigned g_qk[(size_t)B_ * 1024 * 512];   // [b*1024+t][h*64 + (q c2 0-31 | k c2 32-63)], q pre-scaled
__device__ unsigned g_v [(size_t)B_ * 8 * 64 * 512]; // [b*8+h][c][s2]  (f16 pairs)
__device__ unsigned g_h [(size_t)B_ * 1024 * 256];   // [b*1024+t][c2]
__device__ unsigned g_wq[1536 * 256];                // [m][k2]
__device__ unsigned g_wp[512 * 256];

#define CEXP 0.180336880111120f   // 0.125 * log2(e), folded into q

// ---------------------------------------------------------------------------
__device__ __forceinline__ unsigned pack_bf16(float lo, float hi) {
    unsigned r;
    asm("cvt.rn.bf16x2.f32 %0, %1, %2;" : "=r"(r) : "f"(hi), "f"(lo));
    return r;
}
__device__ __forceinline__ unsigned pack_f16(float lo, float hi) {
    unsigned r;
    asm("cvt.rn.f16x2.f32 %0, %1, %2;" : "=r"(r) : "f"(hi), "f"(lo));
    return r;
}
__device__ __forceinline__ unsigned ex2_f16x2(unsigned x) {
    unsigned y;
    asm("ex2.approx.f16x2 %0, %1;" : "=r"(y) : "r"(x));
    return y;
}
__device__ __forceinline__ void mma16(float* d, const unsigned* a, const unsigned* b) {
    asm volatile(
        "mma.sync.aligned.m16n8k16.row.col.f32.bf16.bf16.f32 "
        "{%0,%1,%2,%3}, {%4,%5,%6,%7}, {%8,%9}, {%0,%1,%2,%3};"
        : "+f"(d[0]), "+f"(d[1]), "+f"(d[2]), "+f"(d[3])
        : "r"(a[0]), "r"(a[1]), "r"(a[2]), "r"(a[3]), "r"(b[0]), "r"(b[1]));
}
__device__ __forceinline__ void mma16h(float* d, const unsigned* a, const unsigned* b) {
    asm volatile(
        "mma.sync.aligned.m16n8k16.row.col.f32.f16.f16.f32 "
        "{%0,%1,%2,%3}, {%4,%5,%6,%7}, {%8,%9}, {%0,%1,%2,%3};"
        : "+f"(d[0]), "+f"(d[1]), "+f"(d[2]), "+f"(d[3])
        : "r"(a[0]), "r"(a[1]), "r"(a[2]), "r"(a[3]), "r"(b[0]), "r"(b[1]));
}
#define LDSM4(r0,r1,r2,r3,addr) asm volatile( \
    "ldmatrix.sync.aligned.m8n8.x4.shared.b16 {%0,%1,%2,%3}, [%4];" \
    : "=r"(r0), "=r"(r1), "=r"(r2), "=r"(r3) : "r"(addr))
#define MOVM(d,s) asm("movmatrix.sync.aligned.m8n8.trans.b16 %0, %1;" \
    : "=r"(d) : "r"(s))
#define CP16(dst, src) asm volatile( \
    "cp.async.cg.shared.global [%0], [%1], 16;" :: "r"(dst), "l"(src))
#define CP_COMMIT() asm volatile("cp.async.commit_group;")
#define CP_WAIT(n)  asm volatile("cp.async.wait_group %0;" :: "n"(n))

// ---------------------------------------------------------------------------
// Kernel 0: both weights fp32 [M][512] -> bf16 pairs [m][k2] (merged launch)
// ---------------------------------------------------------------------------
__global__ __launch_bounds__(256) void wconvert2(
    const float* __restrict__ Wq, const float* __restrict__ Wp,
    unsigned* __restrict__ oq, unsigned* __restrict__ op)
{
    int i = blockIdx.x * 256 + threadIdx.x;
    const float* W; unsigned* o;
    if (i < 1536 * 256) { W = Wq; o = oq; }
    else { W = Wp; o = op; i -= 1536 * 256; }
    int m = i >> 8, k2 = i & 255;
    float2 v = *(const float2*)&W[(size_t)m * 512 + 2 * k2];
    o[(size_t)m * 256 + k2] = pack_bf16(v.x, v.y);
}

// ---------------------------------------------------------------------------
// Kernel 1: GroupNorm -> xn bf16 [b*1024+t][c2]  (t-major, GEMM-B-native)
// ---------------------------------------------------------------------------
__global__ __launch_bounds__(256) void groupnorm_t(
    const float* __restrict__ x, const float* __restrict__ gamma,
    const float* __restrict__ beta, unsigned* __restrict__ xn)
{
    extern __shared__ float xs[];          // 16 x 1024 fp32 = 64 KB
    __shared__ float red[18];
    int b = blockIdx.x >> 5, g = blockIdx.x & 31;
    const float4* xp = (const float4*)(x + ((size_t)b * C_ + g * 16) * N_);
    int tid = threadIdx.x;

    float s = 0.f, ss = 0.f;
    #pragma unroll 4
    for (int i = tid; i < 4096; i += 256) {
        float4 v = xp[i];
        ((float4*)xs)[i] = v;
        s  += v.x + v.y + v.z + v.w;
        ss += v.x*v.x + v.y*v.y + v.z*v.z + v.w*v.w;
    }
    #pragma unroll
    for (int o = 16; o; o >>= 1) {
        s  += __shfl_xor_sync(0xffffffffu, s,  o);
        ss += __shfl_xor_sync(0xffffffffu, ss, o);
    }
    int w = tid >> 5;
    if ((tid & 31) == 0) { red[w] = s; red[w + 8] = ss; }
    __syncthreads();
    if (tid == 0) {
        float S = 0.f, SS = 0.f;
        #pragma unroll
        for (int i = 0; i < 8; i++) { S += red[i]; SS += red[i + 8]; }
        float mean = S * (1.f / 16384.f);
        float var  = SS * (1.f / 16384.f) - mean * mean;
        red[16] = mean; red[17] = rsqrtf(var + 1e-5f);
    }
    __syncthreads();
    float mean = red[16], rstd = red[17];

    float wv[16], bv[16];
    #pragma unroll
    for (int c = 0; c < 16; c++) {
        wv[c] = gamma[g * 16 + c] * rstd;
        bv[c] = beta[g * 16 + c] - mean * wv[c];
    }
    unsigned* outp = xn + ((size_t)b << 10) * 256 + g * 8;
    #pragma unroll
    for (int u = 0; u < 4; u++) {
        int t = tid + 256 * u;
        unsigned p[8];
        #pragma unroll
        for (int c2 = 0; c2 < 8; c2++)
            p[c2] = pack_bf16(fmaf(xs[(2*c2)*1024 + t],   wv[2*c2],   bv[2*c2]),
                              fmaf(xs[(2*c2+1)*1024 + t], wv[2*c2+1], bv[2*c2+1]));
        *(uint4*)&outp[(size_t)t * 256]     = *(uint4*)&p[0];
        *(uint4*)&outp[(size_t)t * 256 + 4] = *(uint4*)&p[4];
    }
}

// ---------------------------------------------------------------------------
// Kernel 2/4: bf16 GEMM.  BM=256 x BN=128, BK=32, 3 stages, 512 thr / 16 warps
// (4m x 4n).  Halves activation L2 traffic vs BM=128 (X read 6x not 12x).
// EPI 0: q scaled by CEXP + bf16 [t][c2]; k bf16; v f16 [c][s2].  EPI 1: proj.
// ---------------------------------------------------------------------------
template<int EPI>
__global__ __launch_bounds__(512, 1) void gemm2(
    const unsigned* __restrict__ Wp, const unsigned* __restrict__ Xp,
    const float* __restrict__ bias, const float* __restrict__ res,
    void* __restrict__ out0, unsigned* __restrict__ vout)
{
    extern __shared__ unsigned smg[];
    unsigned* Ws = smg;             // 3 stages x [256][20]
    unsigned* As = smg + 15360;     // 3 stages x [128][20]

    int m0 = blockIdx.x * 256, n0 = blockIdx.y * 128, bz = blockIdx.z;
    Xp += (size_t)bz * 1024 * 256;
    int tid = threadIdx.x, lane = tid & 31, w = tid >> 5;
    int g = lane >> 2, tig = lane & 3;
    int wm = (w & 3) * 64, wn = (w >> 2) * 32;

    unsigned ws_b = (unsigned)__cvta_generic_to_shared(Ws);
    unsigned as_b = (unsigned)__cvta_generic_to_shared(As);

    // prefetch stages 0,1 (1536 CP16 per stage: 1024 W + 512 X)
    #pragma unroll
    for (int st = 0; st < 2; st++) {
        #pragma unroll
        for (int u = 0; u < 3; u++) {
            int q = tid + 512 * u;               // 0..1535
            if (q < 1024) {
                int r = q >> 2, cj = (q & 3) * 4;
                CP16(ws_b + (st * 5120 + r * 20 + cj) * 4,
                     Wp + (size_t)(m0 + r) * 256 + st * 16 + cj);
            } else {
                int r = (q - 1024) >> 2, cj = (q & 3) * 4;
                CP16(as_b + (st * 2560 + r * 20 + cj) * 4,
                     Xp + (size_t)(n0 + r) * 256 + st * 16 + cj);
            }
        }
        CP_COMMIT();
    }

    unsigned aw = ws_b + ((wm + (lane & 15)) * 20 + (lane >> 4) * 4) * 4;
    unsigned bx = as_b + ((wn + (lane & 7) + ((lane >> 4) & 1) * 8) * 20
                          + ((lane >> 3) & 1) * 4) * 4;

    float acc[4][4][4];
    #pragma unroll
    for (int i = 0; i < 4; i++)
        #pragma unroll
        for (int j = 0; j < 4; j++)
            #pragma unroll
            for (int q = 0; q < 4; q++) acc[i][j][q] = 0.f;

    for (int it = 0; it < 16; it++) {
        if (it < 15) { CP_WAIT(1); } else { CP_WAIT(0); }
        __syncthreads();
        if (it + 2 < 16) {
            int st = (it + 2) % 3, k2b = (it + 2) * 16;
            #pragma unroll
            for (int u = 0; u < 3; u++) {
                int q = tid + 512 * u;
                if (q < 1024) {
                    int r = q >> 2, cj = (q & 3) * 4;
                    CP16(ws_b + (st * 5120 + r * 20 + cj) * 4,
                         Wp + (size_t)(m0 + r) * 256 + k2b + cj);
                } else {
                    int r = (q - 1024) >> 2, cj = (q & 3) * 4;
                    CP16(as_b + (st * 2560 + r * 20 + cj) * 4,
                         Xp + (size_t)(n0 + r) * 256 + k2b + cj);
                }
            }
            CP_COMMIT();
        }
        int st = it % 3;
        unsigned awa = aw + st * 20480, bxa = bx + st * 10240;
        #pragma unroll
        for (int ks = 0; ks < 2; ks++) {
            unsigned a[4][4], b[4][2];
            #pragma unroll
            for (int mt = 0; mt < 4; mt++)
                LDSM4(a[mt][0], a[mt][1], a[mt][2], a[mt][3],
                      awa + mt * 1280 + ks * 32);
            #pragma unroll
            for (int np = 0; np < 2; np++)
                LDSM4(b[2*np][0], b[2*np][1], b[2*np+1][0], b[2*np+1][1],
                      bxa + np * 1280 + ks * 32);
            #pragma unroll
            for (int mt = 0; mt < 4; mt++)
                #pragma unroll
                for (int nt = 0; nt < 4; nt++)
                    mma16(acc[mt][nt], a[mt], b[nt]);
        }
    }

    if (EPI == 0) {
        unsigned* qko = (unsigned*)out0 + ((size_t)bz << 10) * 512;
        #pragma unroll
        for (int mt = 0; mt < 4; mt++) {
            int mrow = m0 + wm + mt * 16;
            int hh = mrow / 192, r192 = mrow % 192;
            float b0v = bias[mrow + g], b1v = bias[mrow + 8 + g];
            if (r192 < 128) {               // q|k -> [t][c2] via movmatrix
                float sc = (r192 < 64) ? CEXP : 1.0f;   // fold softmax scale into q
                int c2b = hh * 64 + (r192 >> 1);
                #pragma unroll
                for (int nt = 0; nt < 4; nt++) {
                    unsigned u0 = pack_bf16((acc[mt][nt][0] + b0v) * sc,
                                            (acc[mt][nt][1] + b0v) * sc);
                    unsigned u1 = pack_bf16((acc[mt][nt][2] + b1v) * sc,
                                            (acc[mt][nt][3] + b1v) * sc);
                    unsigned t0r, t1r; MOVM(t0r, u0); MOVM(t1r, u1);
                    size_t tr = (size_t)(n0 + wn + nt * 8 + g) * 512;
                    qko[tr + c2b + tig]     = t0r;
                    qko[tr + c2b + 4 + tig] = t1r;
                }
            } else {                        // v -> [c][s2] native, f16 pairs
                unsigned* vo = vout + (size_t)((bz * 8 + hh) * 64 + (r192 - 128)) * 512;
                #pragma unroll
                for (int nt = 0; nt < 4; nt++) {
                    int s2 = ((n0 + wn + nt * 8) >> 1) + tig;
                    vo[(size_t)g * 512 + s2] =
                        pack_f16(acc[mt][nt][0] + b0v, acc[mt][nt][1] + b0v);
                    vo[(size_t)(g + 8) * 512 + s2] =
                        pack_f16(acc[mt][nt][2] + b1v, acc[mt][nt][3] + b1v);
                }
            }
        }
    } else {
        float* op = (float*)out0 + (size_t)bz * 512 * 1024;
        const float* rp = res + (size_t)bz * 512 * 1024;
        #pragma unroll
        for (int mt = 0; mt < 4; mt++) {
            int mrow = m0 + wm + mt * 16;
            float b0v = bias[mrow + g], b1v = bias[mrow + 8 + g];
            #pragma unroll
            for (int nt = 0; nt < 4; nt++) {
                int tc = n0 + wn + nt * 8 + 2 * tig;
                size_t o0 = (size_t)(mrow + g) * 1024 + tc;
                size_t o1 = (size_t)(mrow + 8 + g) * 1024 + tc;
                float2 r0 = *(const float2*)&rp[o0];
                float2 r1 = *(const float2*)&rp[o1];
                float2 v0 = { acc[mt][nt][0] + b0v + r0.x, acc[mt][nt][1] + b0v + r0.y };
                float2 v1 = { acc[mt][nt][2] + b1v + r1.x, acc[mt][nt][3] + b1v + r1.y };
                *(float2*)&op[o0] = v0;
                *(float2*)&op[o1] = v1;
            }
        }
    }
}

// ---------------------------------------------------------------------------
// Kernel 3: flash attention (byte-identical to the 233.8 winner).
// ---------------------------------------------------------------------------
__global__ __launch_bounds__(256, 2) void attn2(
    const unsigned* __restrict__ qk, const unsigned* __restrict__ vv,
    unsigned* __restrict__ hout)
{
    extern __shared__ unsigned sma[];
    unsigned* Qs = sma;
    unsigned* Ks = sma + 4608;
    unsigned* Vs = sma + 11520;

    int tid = threadIdx.x, lane = tid & 31, w = tid >> 5;
    int g = lane >> 2, tig = lane & 3;
    int qt = blockIdx.x, head = blockIdx.y;
    int bz = head >> 3, hh = head & 7;
    const unsigned* qkb = qk + ((size_t)bz << 10) * 512;
    const unsigned* vb  = vv + (size_t)(bz * 8 + hh) * 64 * 512;
    int t0 = qt * 128;

    unsigned qs_b = (unsigned)__cvta_generic_to_shared(Qs);
    unsigned ks_b = (unsigned)__cvta_generic_to_shared(Ks);
    unsigned vs_b = (unsigned)__cvta_generic_to_shared(Vs);

    #pragma unroll
    for (int u = 0; u < 4; u++) {
        int q = tid + 256 * u;
        int r = q >> 3, cj = (q & 7) * 4;
        CP16(qs_b + (r * 36 + cj) * 4, qkb + (size_t)(t0 + r) * 512 + hh * 64 + cj);
    }
    #pragma unroll
    for (int u = 0; u < 2; u++) {
        int q = tid + 256 * u;
        int r = q >> 3, cj = (q & 7) * 4;
        CP16(ks_b + (r * 36 + cj) * 4, qkb + (size_t)r * 512 + hh * 64 + 32 + cj);
        CP16(vs_b + (r * 36 + cj) * 4, vb + (size_t)r * 512 + cj);
    }
    CP_COMMIT();
    #pragma unroll
    for (int u = 0; u < 2; u++) {
        int q = tid + 256 * u;
        int r = q >> 3, cj = (q & 7) * 4;
        CP16(ks_b + (2304 + r * 36 + cj) * 4,
             qkb + (size_t)(64 + r) * 512 + hh * 64 + 32 + cj);
        CP16(vs_b + (2304 + r * 36 + cj) * 4, vb + (size_t)r * 512 + 32 + cj);
    }
    CP_COMMIT();

    CP_WAIT(1);
    __syncthreads();

    unsigned qa[4][4];
    {
        unsigned qaddr = qs_b + ((w * 16 + (lane & 15)) * 36 + (lane >> 4) * 4) * 4;
        #pragma unroll
        for (int ks = 0; ks < 4; ks++)
            LDSM4(qa[ks][0], qa[ks][1], qa[ks][2], qa[ks][3], qaddr + ks * 32);
    }

    unsigned kvf = (((lane & 7) + ((lane >> 4) & 1) * 8) * 36
                    + ((lane >> 3) & 1) * 4) * 4;

    float lacc[4] = {0.f, 0.f, 0.f, 0.f};
    float o[8][4];
    #pragma unroll
    for (int i = 0; i < 8; i++)
        #pragma unroll
        for (int j = 0; j < 4; j++) o[i][j] = 0.f;

    const unsigned ones2 = 0x3C003C00u;      // f16 {1.0, 1.0}

    for (int it = 0; it < 16; it++) {
        if (it > 0) {
            if (it < 15) { CP_WAIT(1); } else { CP_WAIT(0); }
            __syncthreads();
        }
        if (it + 2 < 16) {
            int st = (it + 2) % 3, s0r = (it + 2) * 64;
            #pragma unroll
            for (int u = 0; u < 2; u++) {
                int q = tid + 256 * u;
                int r = q >> 3, cj = (q & 7) * 4;
                CP16(ks_b + (st * 2304 + r * 36 + cj) * 4,
                     qkb + (size_t)(s0r + r) * 512 + hh * 64 + 32 + cj);
                CP16(vs_b + (st * 2304 + r * 36 + cj) * 4,
                     vb + (size_t)r * 512 + (it + 2) * 32 + cj);
            }
            CP_COMMIT();
        }
        int st = it % 3;
        unsigned kfa = ks_b + kvf + st * 9216;
        unsigned vfa = vs_b + kvf + st * 9216;

        float sc[8][4];
        #pragma unroll
        for (int i = 0; i < 8; i++)
            #pragma unroll
            for (int j = 0; j < 4; j++) sc[i][j] = 0.f;
        #pragma unroll
        for (int ks = 0; ks < 4; ks++) {
            #pragma unroll
            for (int np = 0; np < 4; np++) {
                unsigned b0, b1, b2, b3;
                LDSM4(b0, b1, b2, b3, kfa + np * 2304 + ks * 32);
                unsigned bb0[2] = {b0, b1}, bb1[2] = {b2, b3};
                mma16(sc[2*np],     qa[ks], bb0);
                mma16(sc[2*np + 1], qa[ks], bb1);
            }
        }

        unsigned pu[8][2];
        #pragma unroll
        for (int nt = 0; nt < 8; nt++) {
            pu[nt][0] = ex2_f16x2(pack_f16(sc[nt][0], sc[nt][1]));
            pu[nt][1] = ex2_f16x2(pack_f16(sc[nt][2], sc[nt][3]));
        }

        #pragma unroll
        for (int ks = 0; ks < 4; ks++) {
            unsigned pa[4] = { pu[2*ks][0], pu[2*ks][1],
                               pu[2*ks+1][0], pu[2*ks+1][1] };
            unsigned ob[2] = { ones2, ones2 };
            mma16h(lacc, pa, ob);
            #pragma unroll
            for (int np = 0; np < 4; np++) {
                unsigned b0, b1, b2, b3;
                LDSM4(b0, b1, b2, b3, vfa + np * 2304 + ks * 32);
                unsigned bb0[2] = {b0, b1}, bb1[2] = {b2, b3};
                mma16h(o[2*np],     pa, bb0);
                mma16h(o[2*np + 1], pa, bb1);
            }
        }
    }

    float il0 = 1.f / lacc[0], il1 = 1.f / lacc[2];
    unsigned* hb = hout + ((size_t)bz << 10) * 256 + hh * 32;
    size_t tr0 = (size_t)(t0 + w * 16 + g) * 256;
    size_t tr1 = (size_t)(t0 + w * 16 + g + 8) * 256;
    #pragma unroll
    for (int nt = 0; nt < 8; nt++) {
        hb[tr0 + 4 * nt + tig] = pack_bf16(o[nt][0] * il0, o[nt][1] * il0);
        hb[tr1 + 4 * nt + tig] = pack_bf16(o[nt][2] * il1, o[nt][3] * il1);
    }
}

// ---------------------------------------------------------------------------
extern "C" void kernel_launch(void* const* d_in, const int* in_sizes, int n_in,
                              void* d_out, int out_size)
{
    const float* x      = (const float*)d_in[0];
    const float* gamma  = (const float*)d_in[1];
    const float* beta   = (const float*)d_in[2];
    const float* w_qkv  = (const float*)d_in[3];
    const float* b_qkv  = (const float*)d_in[4];
    const float* w_proj = (const float*)d_in[5];
    const float* b_proj = (const float*)d_in[6];

    void *p_xn, *p_qk, *p_v, *p_h, *p_wq, *p_wp;
    cudaGetSymbolAddress(&p_xn, g_xn);
    cudaGetSymbolAddress(&p_qk, g_qk);
    cudaGetSymbolAddress(&p_v,  g_v);
    cudaGetSymbolAddress(&p_h,  g_h);
    cudaGetSymbolAddress(&p_wq, g_wq);
    cudaGetSymbolAddress(&p_wp, g_wp);

    const int gn_smem   = 16 * 1024 * 4;              // 64 KB
    const int gemm_smem = (3 * 5120 + 3 * 2560) * 4;  // 92160 B (BM=256, BK=32)
    const int attn_smem = (4608 + 2 * 3 * 2304) * 4;  // 73728 B
    cudaFuncSetAttribute(groupnorm_t, cudaFuncAttributeMaxDynamicSharedMemorySize, gn_smem);
    cudaFuncSetAttribute(gemm2<0>, cudaFuncAttributeMaxDynamicSharedMemorySize, gemm_smem);
    cudaFuncSetAttribute(gemm2<1>, cudaFuncAttributeMaxDynamicSharedMemorySize, gemm_smem);
    cudaFuncSetAttribute(attn2, cudaFuncAttributeMaxDynamicSharedMemorySize, attn_smem);

    wconvert2<<<2048, 256>>>(w_qkv, w_proj, (unsigned*)p_wq, (unsigned*)p_wp);
    groupnorm_t<<<B_ * GROUPS, 256, gn_smem>>>(x, gamma, beta, (unsigned*)p_xn);

    gemm2<0><<<dim3(6, 8, B_), 512, gemm_smem>>>(
        (const unsigned*)p_wq, (const unsigned*)p_xn, b_qkv, nullptr,
        p_qk, (unsigned*)p_v);

    attn2<<<dim3(8, B_ * 8), 256, attn_smem>>>(
        (const unsigned*)p_qk, (const unsigned*)p_v, (unsigned*)p_h);

    gemm2<1><<<dim3(2, 8, B_), 512, gemm_smem>>>(
        (const unsigned*)p_wp, (const unsigned*)p_h, b_proj, x,
        d_out, nullptr);
}

// round 15
// speedup vs baseline: 1.0607x; 1.0607x over previous
#include <cuda_runtime.h>
#include <cuda_bf16.h>
#include <cuda_fp16.h>
#include <cstddef>
#include <cstdint>

#define B_      16
#define C_      512
#define N_      1024
#define GROUPS  32

// scratch (u32 = packed bf16x2 / f16x2)
__device__ unsigned g_xn[(size_t)B_ * 1024 * 256];   // [b*1024+t][c2]
__device__ unsigned g_qk[(size_t)B_ * 1024 * 512];   // [b*1024+t][h*64 + (q c2 0-31 | k c2 32-63)], q pre-scaled
__device__ unsigned g_v [(size_t)B_ * 8 * 64 * 512]; // [b*8+h][c][s2]  (f16 pairs)
__device__ unsigned g_h [(size_t)B_ * 1024 * 256];   // [b*1024+t][c2]
__device__ unsigned g_wq[1536 * 256];                // [m][k2]
__device__ unsigned g_wp[512 * 256];

#define CEXP 0.180336880111120f   // 0.125 * log2(e), folded into q

// ---------------------------------------------------------------------------
__device__ __forceinline__ unsigned pack_bf16(float lo, float hi) {
    unsigned r;
    asm("cvt.rn.bf16x2.f32 %0, %1, %2;" : "=r"(r) : "f"(hi), "f"(lo));
    return r;
}
__device__ __forceinline__ unsigned pack_f16(float lo, float hi) {
    unsigned r;
    asm("cvt.rn.f16x2.f32 %0, %1, %2;" : "=r"(r) : "f"(hi), "f"(lo));
    return r;
}
__device__ __forceinline__ unsigned ex2_f16x2(unsigned x) {
    unsigned y;
    asm("ex2.approx.f16x2 %0, %1;" : "=r"(y) : "r"(x));
    return y;
}
__device__ __forceinline__ unsigned hadd2u(unsigned a, unsigned b) {
    unsigned r;
    asm("add.f16x2 %0, %1, %2;" : "=r"(r) : "r"(a), "r"(b));
    return r;
}
__device__ __forceinline__ void mma16(float* d, const unsigned* a, const unsigned* b) {
    asm volatile(
        "mma.sync.aligned.m16n8k16.row.col.f32.bf16.bf16.f32 "
        "{%0,%1,%2,%3}, {%4,%5,%6,%7}, {%8,%9}, {%0,%1,%2,%3};"
        : "+f"(d[0]), "+f"(d[1]), "+f"(d[2]), "+f"(d[3])
        : "r"(a[0]), "r"(a[1]), "r"(a[2]), "r"(a[3]), "r"(b[0]), "r"(b[1]));
}
__device__ __forceinline__ void mma16h(float* d, const unsigned* a, const unsigned* b) {
    asm volatile(
        "mma.sync.aligned.m16n8k16.row.col.f32.f16.f16.f32 "
        "{%0,%1,%2,%3}, {%4,%5,%6,%7}, {%8,%9}, {%0,%1,%2,%3};"
        : "+f"(d[0]), "+f"(d[1]), "+f"(d[2]), "+f"(d[3])
        : "r"(a[0]), "r"(a[1]), "r"(a[2]), "r"(a[3]), "r"(b[0]), "r"(b[1]));
}
#define LDSM4(r0,r1,r2,r3,addr) asm volatile( \
    "ldmatrix.sync.aligned.m8n8.x4.shared.b16 {%0,%1,%2,%3}, [%4];" \
    : "=r"(r0), "=r"(r1), "=r"(r2), "=r"(r3) : "r"(addr))
#define MOVM(d,s) asm("movmatrix.sync.aligned.m8n8.trans.b16 %0, %1;" \
    : "=r"(d) : "r"(s))
#define CP16(dst, src) asm volatile( \
    "cp.async.cg.shared.global [%0], [%1], 16;" :: "r"(dst), "l"(src))
#define CP_COMMIT() asm volatile("cp.async.commit_group;")
#define CP_WAIT(n)  asm volatile("cp.async.wait_group %0;" :: "n"(n))

// ---------------------------------------------------------------------------
// Kernel 0: both weights fp32 [M][512] -> bf16 pairs [m][k2] (merged launch)
// ---------------------------------------------------------------------------
__global__ __launch_bounds__(256) void wconvert2(
    const float* __restrict__ Wq, const float* __restrict__ Wp,
    unsigned* __restrict__ oq, unsigned* __restrict__ op)
{
    int i = blockIdx.x * 256 + threadIdx.x;
    const float* W; unsigned* o;
    if (i < 1536 * 256) { W = Wq; o = oq; }
    else { W = Wp; o = op; i -= 1536 * 256; }
    int m = i >> 8, k2 = i & 255;
    float2 v = *(const float2*)&W[(size_t)m * 512 + 2 * k2];
    o[(size_t)m * 256 + k2] = pack_bf16(v.x, v.y);
}

// ---------------------------------------------------------------------------
// Kernel 1: GroupNorm -> xn bf16 [b*1024+t][c2]  (t-major, GEMM-B-native)
// ---------------------------------------------------------------------------
__global__ __launch_bounds__(256) void groupnorm_t(
    const float* __restrict__ x, const float* __restrict__ gamma,
    const float* __restrict__ beta, unsigned* __restrict__ xn)
{
    extern __shared__ float xs[];          // 16 x 1024 fp32 = 64 KB
    __shared__ float red[18];
    int b = blockIdx.x >> 5, g = blockIdx.x & 31;
    const float4* xp = (const float4*)(x + ((size_t)b * C_ + g * 16) * N_);
    int tid = threadIdx.x;

    float s = 0.f, ss = 0.f;
    #pragma unroll 4
    for (int i = tid; i < 4096; i += 256) {
        float4 v = xp[i];
        ((float4*)xs)[i] = v;
        s  += v.x + v.y + v.z + v.w;
        ss += v.x*v.x + v.y*v.y + v.z*v.z + v.w*v.w;
    }
    #pragma unroll
    for (int o = 16; o; o >>= 1) {
        s  += __shfl_xor_sync(0xffffffffu, s,  o);
        ss += __shfl_xor_sync(0xffffffffu, ss, o);
    }
    int w = tid >> 5;
    if ((tid & 31) == 0) { red[w] = s; red[w + 8] = ss; }
    __syncthreads();
    if (tid == 0) {
        float S = 0.f, SS = 0.f;
        #pragma unroll
        for (int i = 0; i < 8; i++) { S += red[i]; SS += red[i + 8]; }
        float mean = S * (1.f / 16384.f);
        float var  = SS * (1.f / 16384.f) - mean * mean;
        red[16] = mean; red[17] = rsqrtf(var + 1e-5f);
    }
    __syncthreads();
    float mean = red[16], rstd = red[17];

    float wv[16], bv[16];
    #pragma unroll
    for (int c = 0; c < 16; c++) {
        wv[c] = gamma[g * 16 + c] * rstd;
        bv[c] = beta[g * 16 + c] - mean * wv[c];
    }
    unsigned* outp = xn + ((size_t)b << 10) * 256 + g * 8;
    #pragma unroll
    for (int u = 0; u < 4; u++) {
        int t = tid + 256 * u;
        unsigned p[8];
        #pragma unroll
        for (int c2 = 0; c2 < 8; c2++)
            p[c2] = pack_bf16(fmaf(xs[(2*c2)*1024 + t],   wv[2*c2],   bv[2*c2]),
                              fmaf(xs[(2*c2+1)*1024 + t], wv[2*c2+1], bv[2*c2+1]));
        *(uint4*)&outp[(size_t)t * 256]     = *(uint4*)&p[0];
        *(uint4*)&outp[(size_t)t * 256 + 4] = *(uint4*)&p[4];
    }
}

// ---------------------------------------------------------------------------
// Kernel 2/4: bf16 GEMM (proven R13 config: BM=128, BK=32, 3 stages).
// EPI 0: q scaled by CEXP + bf16 [t][c2]; k bf16; v f16 [c][s2].  EPI 1: proj.
// ---------------------------------------------------------------------------
template<int EPI>
__global__ __launch_bounds__(256, 2) void gemm2(
    const unsigned* __restrict__ Wp, const unsigned* __restrict__ Xp,
    const float* __restrict__ bias, const float* __restrict__ res,
    void* __restrict__ out0, unsigned* __restrict__ vout)
{
    extern __shared__ unsigned smg[];
    unsigned* Ws = smg;            // 3 stages x [128][20]
    unsigned* As = smg + 7680;     // 3 stages x [128][20]

    int m0 = blockIdx.x * 128, n0 = blockIdx.y * 128, bz = blockIdx.z;
    Xp += (size_t)bz * 1024 * 256;
    int tid = threadIdx.x, lane = tid & 31, w = tid >> 5;
    int g = lane >> 2, tig = lane & 3;
    int wm = (w & 1) * 64, wn = (w >> 1) * 32;

    unsigned ws_b = (unsigned)__cvta_generic_to_shared(Ws);
    unsigned as_b = (unsigned)__cvta_generic_to_shared(As);

    #pragma unroll
    for (int st = 0; st < 2; st++) {
        #pragma unroll
        for (int u = 0; u < 2; u++) {
            int q = tid + 256 * u;
            int r = q >> 2, cj = (q & 3) * 4;
            CP16(ws_b + (st * 2560 + r * 20 + cj) * 4,
                 Wp + (size_t)(m0 + r) * 256 + st * 16 + cj);
            CP16(as_b + (st * 2560 + r * 20 + cj) * 4,
                 Xp + (size_t)(n0 + r) * 256 + st * 16 + cj);
        }
        CP_COMMIT();
    }

    unsigned aw = ws_b + ((wm + (lane & 15)) * 20 + (lane >> 4) * 4) * 4;
    unsigned bx = as_b + ((wn + (lane & 7) + ((lane >> 4) & 1) * 8) * 20
                          + ((lane >> 3) & 1) * 4) * 4;

    float acc[4][4][4];
    #pragma unroll
    for (int i = 0; i < 4; i++)
        #pragma unroll
        for (int j = 0; j < 4; j++)
            #pragma unroll
            for (int q = 0; q < 4; q++) acc[i][j][q] = 0.f;

    for (int it = 0; it < 16; it++) {
        if (it < 15) { CP_WAIT(1); } else { CP_WAIT(0); }
        __syncthreads();
        if (it + 2 < 16) {
            int st = (it + 2) % 3, k2b = (it + 2) * 16;
            #pragma unroll
            for (int u = 0; u < 2; u++) {
                int q = tid + 256 * u;
                int r = q >> 2, cj = (q & 3) * 4;
                CP16(ws_b + (st * 2560 + r * 20 + cj) * 4,
                     Wp + (size_t)(m0 + r) * 256 + k2b + cj);
                CP16(as_b + (st * 2560 + r * 20 + cj) * 4,
                     Xp + (size_t)(n0 + r) * 256 + k2b + cj);
            }
            CP_COMMIT();
        }
        int st = it % 3;
        unsigned awa = aw + st * 10240, bxa = bx + st * 10240;
        #pragma unroll
        for (int ks = 0; ks < 2; ks++) {
            unsigned a[4][4], b[4][2];
            #pragma unroll
            for (int mt = 0; mt < 4; mt++)
                LDSM4(a[mt][0], a[mt][1], a[mt][2], a[mt][3],
                      awa + mt * 1280 + ks * 32);
            #pragma unroll
            for (int np = 0; np < 2; np++)
                LDSM4(b[2*np][0], b[2*np][1], b[2*np+1][0], b[2*np+1][1],
                      bxa + np * 1280 + ks * 32);
            #pragma unroll
            for (int mt = 0; mt < 4; mt++)
                #pragma unroll
                for (int nt = 0; nt < 4; nt++)
                    mma16(acc[mt][nt], a[mt], b[nt]);
        }
    }

    if (EPI == 0) {
        unsigned* qko = (unsigned*)out0 + ((size_t)bz << 10) * 512;
        #pragma unroll
        for (int mt = 0; mt < 4; mt++) {
            int mrow = m0 + wm + mt * 16;
            int hh = mrow / 192, r192 = mrow % 192;
            float b0v = bias[mrow + g], b1v = bias[mrow + 8 + g];
            if (r192 < 128) {               // q|k -> [t][c2] via movmatrix
                float sc = (r192 < 64) ? CEXP : 1.0f;   // fold softmax scale into q
                int c2b = hh * 64 + (r192 >> 1);
                #pragma unroll
                for (int nt = 0; nt < 4; nt++) {
                    unsigned u0 = pack_bf16((acc[mt][nt][0] + b0v) * sc,
                                            (acc[mt][nt][1] + b0v) * sc);
                    unsigned u1 = pack_bf16((acc[mt][nt][2] + b1v) * sc,
                                            (acc[mt][nt][3] + b1v) * sc);
                    unsigned t0r, t1r; MOVM(t0r, u0); MOVM(t1r, u1);
                    size_t tr = (size_t)(n0 + wn + nt * 8 + g) * 512;
                    qko[tr + c2b + tig]     = t0r;
                    qko[tr + c2b + 4 + tig] = t1r;
                }
            } else {                        // v -> [c][s2] native, f16 pairs
                unsigned* vo = vout + (size_t)((bz * 8 + hh) * 64 + (r192 - 128)) * 512;
                #pragma unroll
                for (int nt = 0; nt < 4; nt++) {
                    int s2 = ((n0 + wn + nt * 8) >> 1) + tig;
                    vo[(size_t)g * 512 + s2] =
                        pack_f16(acc[mt][nt][0] + b0v, acc[mt][nt][1] + b0v);
                    vo[(size_t)(g + 8) * 512 + s2] =
                        pack_f16(acc[mt][nt][2] + b1v, acc[mt][nt][3] + b1v);
                }
            }
        }
    } else {
        float* op = (float*)out0 + (size_t)bz * 512 * 1024;
        const float* rp = res + (size_t)bz * 512 * 1024;
        #pragma unroll
        for (int mt = 0; mt < 4; mt++) {
            int mrow = m0 + wm + mt * 16;
            float b0v = bias[mrow + g], b1v = bias[mrow + 8 + g];
            #pragma unroll
            for (int nt = 0; nt < 4; nt++) {
                int tc = n0 + wn + nt * 8 + 2 * tig;
                size_t o0 = (size_t)(mrow + g) * 1024 + tc;
                size_t o1 = (size_t)(mrow + 8 + g) * 1024 + tc;
                float2 r0 = *(const float2*)&rp[o0];
                float2 r1 = *(const float2*)&rp[o1];
                float2 v0 = { acc[mt][nt][0] + b0v + r0.x, acc[mt][nt][1] + b0v + r0.y };
                float2 v1 = { acc[mt][nt][2] + b1v + r1.x, acc[mt][nt][3] + b1v + r1.y };
                *(float2*)&op[o0] = v0;
                *(float2*)&op[o1] = v1;
            }
        }
    }
}

// ---------------------------------------------------------------------------
// Kernel 3: flash attention.  Change vs 233.8 winner: l row-sums moved off the
// tensor pipe (ones-mma removed) onto the idle fma pipe via an HADD2 tree over
// the packed f16x2 P fragments + fp32 accumulation; quad-shuffle reduce at end.
// ---------------------------------------------------------------------------
__global__ __launch_bounds__(256, 2) void attn2(
    const unsigned* __restrict__ qk, const unsigned* __restrict__ vv,
    unsigned* __restrict__ hout)
{
    extern __shared__ unsigned sma[];
    unsigned* Qs = sma;
    unsigned* Ks = sma + 4608;
    unsigned* Vs = sma + 11520;

    int tid = threadIdx.x, lane = tid & 31, w = tid >> 5;
    int g = lane >> 2, tig = lane & 3;
    int qt = blockIdx.x, head = blockIdx.y;
    int bz = head >> 3, hh = head & 7;
    const unsigned* qkb = qk + ((size_t)bz << 10) * 512;
    const unsigned* vb  = vv + (size_t)(bz * 8 + hh) * 64 * 512;
    int t0 = qt * 128;

    unsigned qs_b = (unsigned)__cvta_generic_to_shared(Qs);
    unsigned ks_b = (unsigned)__cvta_generic_to_shared(Ks);
    unsigned vs_b = (unsigned)__cvta_generic_to_shared(Vs);

    #pragma unroll
    for (int u = 0; u < 4; u++) {
        int q = tid + 256 * u;
        int r = q >> 3, cj = (q & 7) * 4;
        CP16(qs_b + (r * 36 + cj) * 4, qkb + (size_t)(t0 + r) * 512 + hh * 64 + cj);
    }
    #pragma unroll
    for (int u = 0; u < 2; u++) {
        int q = tid + 256 * u;
        int r = q >> 3, cj = (q & 7) * 4;
        CP16(ks_b + (r * 36 + cj) * 4, qkb + (size_t)r * 512 + hh * 64 + 32 + cj);
        CP16(vs_b + (r * 36 + cj) * 4, vb + (size_t)r * 512 + cj);
    }
    CP_COMMIT();
    #pragma unroll
    for (int u = 0; u < 2; u++) {
        int q = tid + 256 * u;
        int r = q >> 3, cj = (q & 7) * 4;
        CP16(ks_b + (2304 + r * 36 + cj) * 4,
             qkb + (size_t)(64 + r) * 512 + hh * 64 + 32 + cj);
        CP16(vs_b + (2304 + r * 36 + cj) * 4, vb + (size_t)r * 512 + 32 + cj);
    }
    CP_COMMIT();

    CP_WAIT(1);
    __syncthreads();

    unsigned qa[4][4];
    {
        unsigned qaddr = qs_b + ((w * 16 + (lane & 15)) * 36 + (lane >> 4) * 4) * 4;
        #pragma unroll
        for (int ks = 0; ks < 4; ks++)
            LDSM4(qa[ks][0], qa[ks][1], qa[ks][2], qa[ks][3], qaddr + ks * 32);
    }

    unsigned kvf = (((lane & 7) + ((lane >> 4) & 1) * 8) * 36
                    + ((lane >> 3) & 1) * 4) * 4;

    float l0 = 0.f, l1 = 0.f;
    float o[8][4];
    #pragma unroll
    for (int i = 0; i < 8; i++)
        #pragma unroll
        for (int j = 0; j < 4; j++) o[i][j] = 0.f;

    for (int it = 0; it < 16; it++) {
        if (it > 0) {
            if (it < 15) { CP_WAIT(1); } else { CP_WAIT(0); }
            __syncthreads();
        }
        if (it + 2 < 16) {
            int st = (it + 2) % 3, s0r = (it + 2) * 64;
            #pragma unroll
            for (int u = 0; u < 2; u++) {
                int q = tid + 256 * u;
                int r = q >> 3, cj = (q & 7) * 4;
                CP16(ks_b + (st * 2304 + r * 36 + cj) * 4,
                     qkb + (size_t)(s0r + r) * 512 + hh * 64 + 32 + cj);
                CP16(vs_b + (st * 2304 + r * 36 + cj) * 4,
                     vb + (size_t)r * 512 + (it + 2) * 32 + cj);
            }
            CP_COMMIT();
        }
        int st = it % 3;
        unsigned kfa = ks_b + kvf + st * 9216;
        unsigned vfa = vs_b + kvf + st * 9216;

        // S = Q' K^T  (already scaled by 0.125*log2e via q)
        float sc[8][4];
        #pragma unroll
        for (int i = 0; i < 8; i++)
            #pragma unroll
            for (int j = 0; j < 4; j++) sc[i][j] = 0.f;
        #pragma unroll
        for (int ks = 0; ks < 4; ks++) {
            #pragma unroll
            for (int np = 0; np < 4; np++) {
                unsigned b0, b1, b2, b3;
                LDSM4(b0, b1, b2, b3, kfa + np * 2304 + ks * 32);
                unsigned bb0[2] = {b0, b1}, bb1[2] = {b2, b3};
                mma16(sc[2*np],     qa[ks], bb0);
                mma16(sc[2*np + 1], qa[ks], bb1);
            }
        }

        // P = exp2(S) in f16x2
        unsigned pu[8][2];
        #pragma unroll
        for (int nt = 0; nt < 8; nt++) {
            pu[nt][0] = ex2_f16x2(pack_f16(sc[nt][0], sc[nt][1]));
            pu[nt][1] = ex2_f16x2(pack_f16(sc[nt][2], sc[nt][3]));
        }

        // l row-sums on the fma pipe: HADD2 tree over the 8 packed fragments
        {
            unsigned t00 = hadd2u(pu[0][0], pu[1][0]);
            unsigned t01 = hadd2u(pu[2][0], pu[3][0]);
            unsigned t02 = hadd2u(pu[4][0], pu[5][0]);
            unsigned t03 = hadd2u(pu[6][0], pu[7][0]);
            unsigned t0s = hadd2u(hadd2u(t00, t01), hadd2u(t02, t03));
            float2 f0 = __half22float2(*(__half2*)&t0s);
            l0 += f0.x + f0.y;
            unsigned t10 = hadd2u(pu[0][1], pu[1][1]);
            unsigned t11 = hadd2u(pu[2][1], pu[3][1]);
            unsigned t12 = hadd2u(pu[4][1], pu[5][1]);
            unsigned t13 = hadd2u(pu[6][1], pu[7][1]);
            unsigned t1s = hadd2u(hadd2u(t10, t11), hadd2u(t12, t13));
            float2 f1 = __half22float2(*(__half2*)&t1s);
            l1 += f1.x + f1.y;
        }

        // O += P V^T
        #pragma unroll
        for (int ks = 0; ks < 4; ks++) {
            unsigned pa[4] = { pu[2*ks][0], pu[2*ks][1],
                               pu[2*ks+1][0], pu[2*ks+1][1] };
            #pragma unroll
            for (int np = 0; np < 4; np++) {
                unsigned b0, b1, b2, b3;
                LDSM4(b0, b1, b2, b3, vfa + np * 2304 + ks * 32);
                unsigned bb0[2] = {b0, b1}, bb1[2] = {b2, b3};
                mma16h(o[2*np],     pa, bb0);
                mma16h(o[2*np + 1], pa, bb1);
            }
        }
    }

    // quad-reduce l (each thread holds 16 of 64 columns per row)
    l0 += __shfl_xor_sync(0xffffffffu, l0, 1);
    l0 += __shfl_xor_sync(0xffffffffu, l0, 2);
    l1 += __shfl_xor_sync(0xffffffffu, l1, 1);
    l1 += __shfl_xor_sync(0xffffffffu, l1, 2);

    float il0 = 1.f / l0, il1 = 1.f / l1;
    unsigned* hb = hout + ((size_t)bz << 10) * 256 + hh * 32;
    size_t tr0 = (size_t)(t0 + w * 16 + g) * 256;
    size_t tr1 = (size_t)(t0 + w * 16 + g + 8) * 256;
    #pragma unroll
    for (int nt = 0; nt < 8; nt++) {
        hb[tr0 + 4 * nt + tig] = pack_bf16(o[nt][0] * il0, o[nt][1] * il0);
        hb[tr1 + 4 * nt + tig] = pack_bf16(o[nt][2] * il1, o[nt][3] * il1);
    }
}

// ---------------------------------------------------------------------------
extern "C" void kernel_launch(void* const* d_in, const int* in_sizes, int n_in,
                              void* d_out, int out_size)
{
    const float* x      = (const float*)d_in[0];
    const float* gamma  = (const float*)d_in[1];
    const float* beta   = (const float*)d_in[2];
    const float* w_qkv  = (const float*)d_in[3];
    const float* b_qkv  = (const float*)d_in[4];
    const float* w_proj = (const float*)d_in[5];
    const float* b_proj = (const float*)d_in[6];

    void *p_xn, *p_qk, *p_v, *p_h, *p_wq, *p_wp;
    cudaGetSymbolAddress(&p_xn, g_xn);
    cudaGetSymbolAddress(&p_qk, g_qk);
    cudaGetSymbolAddress(&p_v,  g_v);
    cudaGetSymbolAddress(&p_h,  g_h);
    cudaGetSymbolAddress(&p_wq, g_wq);
    cudaGetSymbolAddress(&p_wp, g_wp);

    const int gn_smem   = 16 * 1024 * 4;              // 64 KB
    const int gemm_smem = 2 * 3 * 2560 * 4;           // 61440 B (BK=32, 3 stages)
    const int attn_smem = (4608 + 2 * 3 * 2304) * 4;  // 73728 B
    cudaFuncSetAttribute(groupnorm_t, cudaFuncAttributeMaxDynamicSharedMemorySize, gn_smem);
    cudaFuncSetAttribute(gemm2<0>, cudaFuncAttributeMaxDynamicSharedMemorySize, gemm_smem);
    cudaFuncSetAttribute(gemm2<1>, cudaFuncAttributeMaxDynamicSharedMemorySize, gemm_smem);
    cudaFuncSetAttribute(attn2, cudaFuncAttributeMaxDynamicSharedMemorySize, attn_smem);

    wconvert2<<<2048, 256>>>(w_qkv, w_proj, (unsigned*)p_wq, (unsigned*)p_wp);
    groupnorm_t<<<B_ * GROUPS, 256, gn_smem>>>(x, gamma, beta, (unsigned*)p_xn);

    gemm2<0><<<dim3(12, 8, B_), 256, gemm_smem>>>(
        (const unsigned*)p_wq, (const unsigned*)p_xn, b_qkv, nullptr,
        p_qk, (unsigned*)p_v);

    attn2<<<dim3(8, B_ * 8), 256, attn_smem>>>(
        (const unsigned*)p_qk, (const unsigned*)p_v, (unsigned*)p_h);

    gemm2<1><<<dim3(4, 8, B_), 256, gemm_smem>>>(
        (const unsigned*)p_wp, (const unsigned*)p_h, b_proj, x,
        d_out, nullptr);
}

// round 16
// speedup vs baseline: 1.0639x; 1.0030x over previous
#include <cuda_runtime.h>
#include <cuda_bf16.h>
#include <cuda_fp16.h>
#include <cstddef>
#include <cstdint>

#define B_      16
#define C_      512
#define N_      1024
#define GROUPS  32

// scratch (u32 = packed bf16x2 / f16x2)
__device__ unsigned g_xn[(size_t)B_ * 1024 * 256];   // [b*1024+t][c2]
__device__ unsigned g_qk[(size_t)B_ * 1024 * 512];   // [b*1024+t][h*64 + (q c2 0-31 | k c2 32-63)], q pre-scaled
__device__ unsigned g_v [(size_t)B_ * 8 * 64 * 512]; // [b*8+h][c][s2]  (f16 pairs)
__device__ unsigned g_h [(size_t)B_ * 1024 * 256];   // [b*1024+t][c2]
__device__ unsigned g_wq[1536 * 256];                // [m][k2]
__device__ unsigned g_wp[512 * 256];

#define CEXP 0.180336880111120f   // 0.125 * log2(e), folded into q

// ---------------------------------------------------------------------------
__device__ __forceinline__ unsigned pack_bf16(float lo, float hi) {
    unsigned r;
    asm("cvt.rn.bf16x2.f32 %0, %1, %2;" : "=r"(r) : "f"(hi), "f"(lo));
    return r;
}
__device__ __forceinline__ unsigned pack_f16(float lo, float hi) {
    unsigned r;
    asm("cvt.rn.f16x2.f32 %0, %1, %2;" : "=r"(r) : "f"(hi), "f"(lo));
    return r;
}
__device__ __forceinline__ unsigned ex2_f16x2(unsigned x) {
    unsigned y;
    asm("ex2.approx.f16x2 %0, %1;" : "=r"(y) : "r"(x));
    return y;
}
__device__ __forceinline__ unsigned hadd2u(unsigned a, unsigned b) {
    unsigned r;
    asm("add.f16x2 %0, %1, %2;" : "=r"(r) : "r"(a), "r"(b));
    return r;
}
__device__ __forceinline__ void mma16(float* d, const unsigned* a, const unsigned* b) {
    asm volatile(
        "mma.sync.aligned.m16n8k16.row.col.f32.bf16.bf16.f32 "
        "{%0,%1,%2,%3}, {%4,%5,%6,%7}, {%8,%9}, {%0,%1,%2,%3};"
        : "+f"(d[0]), "+f"(d[1]), "+f"(d[2]), "+f"(d[3])
        : "r"(a[0]), "r"(a[1]), "r"(a[2]), "r"(a[3]), "r"(b[0]), "r"(b[1]));
}
__device__ __forceinline__ void mma16h(float* d, const unsigned* a, const unsigned* b) {
    asm volatile(
        "mma.sync.aligned.m16n8k16.row.col.f32.f16.f16.f32 "
        "{%0,%1,%2,%3}, {%4,%5,%6,%7}, {%8,%9}, {%0,%1,%2,%3};"
        : "+f"(d[0]), "+f"(d[1]), "+f"(d[2]), "+f"(d[3])
        : "r"(a[0]), "r"(a[1]), "r"(a[2]), "r"(a[3]), "r"(b[0]), "r"(b[1]));
}
#define LDSM4(r0,r1,r2,r3,addr) asm volatile( \
    "ldmatrix.sync.aligned.m8n8.x4.shared.b16 {%0,%1,%2,%3}, [%4];" \
    : "=r"(r0), "=r"(r1), "=r"(r2), "=r"(r3) : "r"(addr))
#define MOVM(d,s) asm("movmatrix.sync.aligned.m8n8.trans.b16 %0, %1;" \
    : "=r"(d) : "r"(s))
#define CP16(dst, src) asm volatile( \
    "cp.async.cg.shared.global [%0], [%1], 16;" :: "r"(dst), "l"(src))
#define CP_COMMIT() asm volatile("cp.async.commit_group;")
#define CP_WAIT(n)  asm volatile("cp.async.wait_group %0;" :: "n"(n))

// ---------------------------------------------------------------------------
// Kernel 0: both weights fp32 [M][512] -> bf16 pairs [m][k2] (merged launch)
// ---------------------------------------------------------------------------
__global__ __launch_bounds__(256) void wconvert2(
    const float* __restrict__ Wq, const float* __restrict__ Wp,
    unsigned* __restrict__ oq, unsigned* __restrict__ op)
{
    int i = blockIdx.x * 256 + threadIdx.x;
    const float* W; unsigned* o;
    if (i < 1536 * 256) { W = Wq; o = oq; }
    else { W = Wp; o = op; i -= 1536 * 256; }
    int m = i >> 8, k2 = i & 255;
    float2 v = *(const float2*)&W[(size_t)m * 512 + 2 * k2];
    o[(size_t)m * 256 + k2] = pack_bf16(v.x, v.y);
}

// ---------------------------------------------------------------------------
// Kernel 1: GroupNorm -> xn bf16 [b*1024+t][c2]  (t-major, GEMM-B-native)
// ---------------------------------------------------------------------------
__global__ __launch_bounds__(256) void groupnorm_t(
    const float* __restrict__ x, const float* __restrict__ gamma,
    const float* __restrict__ beta, unsigned* __restrict__ xn)
{
    extern __shared__ float xs[];          // 16 x 1024 fp32 = 64 KB
    __shared__ float red[18];
    int b = blockIdx.x >> 5, g = blockIdx.x & 31;
    const float4* xp = (const float4*)(x + ((size_t)b * C_ + g * 16) * N_);
    int tid = threadIdx.x;

    float s = 0.f, ss = 0.f;
    #pragma unroll 4
    for (int i = tid; i < 4096; i += 256) {
        float4 v = xp[i];
        ((float4*)xs)[i] = v;
        s  += v.x + v.y + v.z + v.w;
        ss += v.x*v.x + v.y*v.y + v.z*v.z + v.w*v.w;
    }
    #pragma unroll
    for (int o = 16; o; o >>= 1) {
        s  += __shfl_xor_sync(0xffffffffu, s,  o);
        ss += __shfl_xor_sync(0xffffffffu, ss, o);
    }
    int w = tid >> 5;
    if ((tid & 31) == 0) { red[w] = s; red[w + 8] = ss; }
    __syncthreads();
    if (tid == 0) {
        float S = 0.f, SS = 0.f;
        #pragma unroll
        for (int i = 0; i < 8; i++) { S += red[i]; SS += red[i + 8]; }
        float mean = S * (1.f / 16384.f);
        float var  = SS * (1.f / 16384.f) - mean * mean;
        red[16] = mean; red[17] = rsqrtf(var + 1e-5f);
    }
    __syncthreads();
    float mean = red[16], rstd = red[17];

    float wv[16], bv[16];
    #pragma unroll
    for (int c = 0; c < 16; c++) {
        wv[c] = gamma[g * 16 + c] * rstd;
        bv[c] = beta[g * 16 + c] - mean * wv[c];
    }
    unsigned* outp = xn + ((size_t)b << 10) * 256 + g * 8;
    #pragma unroll
    for (int u = 0; u < 4; u++) {
        int t = tid + 256 * u;
        unsigned p[8];
        #pragma unroll
        for (int c2 = 0; c2 < 8; c2++)
            p[c2] = pack_bf16(fmaf(xs[(2*c2)*1024 + t],   wv[2*c2],   bv[2*c2]),
                              fmaf(xs[(2*c2+1)*1024 + t], wv[2*c2+1], bv[2*c2+1]));
        *(uint4*)&outp[(size_t)t * 256]     = *(uint4*)&p[0];
        *(uint4*)&outp[(size_t)t * 256 + 4] = *(uint4*)&p[4];
    }
}

// ---------------------------------------------------------------------------
// Kernel 2/4: bf16 GEMM (frozen R13 config: BM=128, BK=32, 3 stages).
// EPI 0: q scaled by CEXP + bf16 [t][c2]; k bf16; v f16 [c][s2].  EPI 1: proj.
// ---------------------------------------------------------------------------
template<int EPI>
__global__ __launch_bounds__(256, 2) void gemm2(
    const unsigned* __restrict__ Wp, const unsigned* __restrict__ Xp,
    const float* __restrict__ bias, const float* __restrict__ res,
    void* __restrict__ out0, unsigned* __restrict__ vout)
{
    extern __shared__ unsigned smg[];
    unsigned* Ws = smg;            // 3 stages x [128][20]
    unsigned* As = smg + 7680;     // 3 stages x [128][20]

    int m0 = blockIdx.x * 128, n0 = blockIdx.y * 128, bz = blockIdx.z;
    Xp += (size_t)bz * 1024 * 256;
    int tid = threadIdx.x, lane = tid & 31, w = tid >> 5;
    int g = lane >> 2, tig = lane & 3;
    int wm = (w & 1) * 64, wn = (w >> 1) * 32;

    unsigned ws_b = (unsigned)__cvta_generic_to_shared(Ws);
    unsigned as_b = (unsigned)__cvta_generic_to_shared(As);

    #pragma unroll
    for (int st = 0; st < 2; st++) {
        #pragma unroll
        for (int u = 0; u < 2; u++) {
            int q = tid + 256 * u;
            int r = q >> 2, cj = (q & 3) * 4;
            CP16(ws_b + (st * 2560 + r * 20 + cj) * 4,
                 Wp + (size_t)(m0 + r) * 256 + st * 16 + cj);
            CP16(as_b + (st * 2560 + r * 20 + cj) * 4,
                 Xp + (size_t)(n0 + r) * 256 + st * 16 + cj);
        }
        CP_COMMIT();
    }

    unsigned aw = ws_b + ((wm + (lane & 15)) * 20 + (lane >> 4) * 4) * 4;
    unsigned bx = as_b + ((wn + (lane & 7) + ((lane >> 4) & 1) * 8) * 20
                          + ((lane >> 3) & 1) * 4) * 4;

    float acc[4][4][4];
    #pragma unroll
    for (int i = 0; i < 4; i++)
        #pragma unroll
        for (int j = 0; j < 4; j++)
            #pragma unroll
            for (int q = 0; q < 4; q++) acc[i][j][q] = 0.f;

    for (int it = 0; it < 16; it++) {
        if (it < 15) { CP_WAIT(1); } else { CP_WAIT(0); }
        __syncthreads();
        if (it + 2 < 16) {
            int st = (it + 2) % 3, k2b = (it + 2) * 16;
            #pragma unroll
            for (int u = 0; u < 2; u++) {
                int q = tid + 256 * u;
                int r = q >> 2, cj = (q & 3) * 4;
                CP16(ws_b + (st * 2560 + r * 20 + cj) * 4,
                     Wp + (size_t)(m0 + r) * 256 + k2b + cj);
                CP16(as_b + (st * 2560 + r * 20 + cj) * 4,
                     Xp + (size_t)(n0 + r) * 256 + k2b + cj);
            }
            CP_COMMIT();
        }
        int st = it % 3;
        unsigned awa = aw + st * 10240, bxa = bx + st * 10240;
        #pragma unroll
        for (int ks = 0; ks < 2; ks++) {
            unsigned a[4][4], b[4][2];
            #pragma unroll
            for (int mt = 0; mt < 4; mt++)
                LDSM4(a[mt][0], a[mt][1], a[mt][2], a[mt][3],
                      awa + mt * 1280 + ks * 32);
            #pragma unroll
            for (int np = 0; np < 2; np++)
                LDSM4(b[2*np][0], b[2*np][1], b[2*np+1][0], b[2*np+1][1],
                      bxa + np * 1280 + ks * 32);
            #pragma unroll
            for (int mt = 0; mt < 4; mt++)
                #pragma unroll
                for (int nt = 0; nt < 4; nt++)
                    mma16(acc[mt][nt], a[mt], b[nt]);
        }
    }

    if (EPI == 0) {
        unsigned* qko = (unsigned*)out0 + ((size_t)bz << 10) * 512;
        #pragma unroll
        for (int mt = 0; mt < 4; mt++) {
            int mrow = m0 + wm + mt * 16;
            int hh = mrow / 192, r192 = mrow % 192;
            float b0v = bias[mrow + g], b1v = bias[mrow + 8 + g];
            if (r192 < 128) {               // q|k -> [t][c2] via movmatrix
                float sc = (r192 < 64) ? CEXP : 1.0f;   // fold softmax scale into q
                int c2b = hh * 64 + (r192 >> 1);
                #pragma unroll
                for (int nt = 0; nt < 4; nt++) {
                    unsigned u0 = pack_bf16((acc[mt][nt][0] + b0v) * sc,
                                            (acc[mt][nt][1] + b0v) * sc);
                    unsigned u1 = pack_bf16((acc[mt][nt][2] + b1v) * sc,
                                            (acc[mt][nt][3] + b1v) * sc);
                    unsigned t0r, t1r; MOVM(t0r, u0); MOVM(t1r, u1);
                    size_t tr = (size_t)(n0 + wn + nt * 8 + g) * 512;
                    qko[tr + c2b + tig]     = t0r;
                    qko[tr + c2b + 4 + tig] = t1r;
                }
            } else {                        // v -> [c][s2] native, f16 pairs
                unsigned* vo = vout + (size_t)((bz * 8 + hh) * 64 + (r192 - 128)) * 512;
                #pragma unroll
                for (int nt = 0; nt < 4; nt++) {
                    int s2 = ((n0 + wn + nt * 8) >> 1) + tig;
                    vo[(size_t)g * 512 + s2] =
                        pack_f16(acc[mt][nt][0] + b0v, acc[mt][nt][1] + b0v);
                    vo[(size_t)(g + 8) * 512 + s2] =
                        pack_f16(acc[mt][nt][2] + b1v, acc[mt][nt][3] + b1v);
                }
            }
        }
    } else {
        float* op = (float*)out0 + (size_t)bz * 512 * 1024;
        const float* rp = res + (size_t)bz * 512 * 1024;
        #pragma unroll
        for (int mt = 0; mt < 4; mt++) {
            int mrow = m0 + wm + mt * 16;
            float b0v = bias[mrow + g], b1v = bias[mrow + 8 + g];
            #pragma unroll
            for (int nt = 0; nt < 4; nt++) {
                int tc = n0 + wn + nt * 8 + 2 * tig;
                size_t o0 = (size_t)(mrow + g) * 1024 + tc;
                size_t o1 = (size_t)(mrow + 8 + g) * 1024 + tc;
                float2 r0 = *(const float2*)&rp[o0];
                float2 r1 = *(const float2*)&rp[o1];
                float2 v0 = { acc[mt][nt][0] + b0v + r0.x, acc[mt][nt][1] + b0v + r0.y };
                float2 v1 = { acc[mt][nt][2] + b1v + r1.x, acc[mt][nt][3] + b1v + r1.y };
                *(float2*)&op[o0] = v0;
                *(float2*)&op[o1] = v1;
            }
        }
    }
}

// ---------------------------------------------------------------------------
// Kernel 3: flash attention.  Change vs 232.0 winner: KV pipeline deepened to
// 4 stages with CP_WAIT(2) (two stages always in flight -> per-iter waits
// rarely block).  Stage written at iter it is (it+3)%4 == (it-1)%4, whose
// readers passed this iter's barrier -> same reuse safety as 3-stage.
// ---------------------------------------------------------------------------
__global__ __launch_bounds__(256, 2) void attn2(
    const unsigned* __restrict__ qk, const unsigned* __restrict__ vv,
    unsigned* __restrict__ hout)
{
    extern __shared__ unsigned sma[];
    unsigned* Qs = sma;            // [128][36]
    unsigned* Ks = sma + 4608;     // 4 stages x [64][36]
    unsigned* Vs = sma + 13824;    // 4 stages x [64][36]

    int tid = threadIdx.x, lane = tid & 31, w = tid >> 5;
    int g = lane >> 2, tig = lane & 3;
    int qt = blockIdx.x, head = blockIdx.y;
    int bz = head >> 3, hh = head & 7;
    const unsigned* qkb = qk + ((size_t)bz << 10) * 512;
    const unsigned* vb  = vv + (size_t)(bz * 8 + hh) * 64 * 512;
    int t0 = qt * 128;

    unsigned qs_b = (unsigned)__cvta_generic_to_shared(Qs);
    unsigned ks_b = (unsigned)__cvta_generic_to_shared(Ks);
    unsigned vs_b = (unsigned)__cvta_generic_to_shared(Vs);

    // group 0: Q + KV stage 0
    #pragma unroll
    for (int u = 0; u < 4; u++) {
        int q = tid + 256 * u;
        int r = q >> 3, cj = (q & 7) * 4;
        CP16(qs_b + (r * 36 + cj) * 4, qkb + (size_t)(t0 + r) * 512 + hh * 64 + cj);
    }
    #pragma unroll
    for (int u = 0; u < 2; u++) {
        int q = tid + 256 * u;
        int r = q >> 3, cj = (q & 7) * 4;
        CP16(ks_b + (r * 36 + cj) * 4, qkb + (size_t)r * 512 + hh * 64 + 32 + cj);
        CP16(vs_b + (r * 36 + cj) * 4, vb + (size_t)r * 512 + cj);
    }
    CP_COMMIT();
    // groups 1,2: KV stages 1,2
    #pragma unroll
    for (int st = 1; st < 3; st++) {
        #pragma unroll
        for (int u = 0; u < 2; u++) {
            int q = tid + 256 * u;
            int r = q >> 3, cj = (q & 7) * 4;
            CP16(ks_b + (st * 2304 + r * 36 + cj) * 4,
                 qkb + (size_t)(st * 64 + r) * 512 + hh * 64 + 32 + cj);
            CP16(vs_b + (st * 2304 + r * 36 + cj) * 4,
                 vb + (size_t)r * 512 + st * 32 + cj);
        }
        CP_COMMIT();
    }

    CP_WAIT(2);
    __syncthreads();

    unsigned qa[4][4];
    {
        unsigned qaddr = qs_b + ((w * 16 + (lane & 15)) * 36 + (lane >> 4) * 4) * 4;
        #pragma unroll
        for (int ks = 0; ks < 4; ks++)
            LDSM4(qa[ks][0], qa[ks][1], qa[ks][2], qa[ks][3], qaddr + ks * 32);
    }

    unsigned kvf = (((lane & 7) + ((lane >> 4) & 1) * 8) * 36
                    + ((lane >> 3) & 1) * 4) * 4;

    float l0 = 0.f, l1 = 0.f;
    float o[8][4];
    #pragma unroll
    for (int i = 0; i < 8; i++)
        #pragma unroll
        for (int j = 0; j < 4; j++) o[i][j] = 0.f;

    for (int it = 0; it < 16; it++) {
        if (it > 0) {
            if (it < 14) { CP_WAIT(2); }
            else if (it == 14) { CP_WAIT(1); }
            else { CP_WAIT(0); }
            __syncthreads();
        }
        if (it + 3 < 16) {
            int st = (it + 3) & 3, s0r = (it + 3) * 64;
            #pragma unroll
            for (int u = 0; u < 2; u++) {
                int q = tid + 256 * u;
                int r = q >> 3, cj = (q & 7) * 4;
                CP16(ks_b + (st * 2304 + r * 36 + cj) * 4,
                     qkb + (size_t)(s0r + r) * 512 + hh * 64 + 32 + cj);
                CP16(vs_b + (st * 2304 + r * 36 + cj) * 4,
                     vb + (size_t)r * 512 + (it + 3) * 32 + cj);
            }
            CP_COMMIT();
        }
        int st = it & 3;
        unsigned kfa = ks_b + kvf + st * 9216;
        unsigned vfa = vs_b + kvf + st * 9216;

        // S = Q' K^T  (already scaled by 0.125*log2e via q)
        float sc[8][4];
        #pragma unroll
        for (int i = 0; i < 8; i++)
            #pragma unroll
            for (int j = 0; j < 4; j++) sc[i][j] = 0.f;
        #pragma unroll
        for (int ks = 0; ks < 4; ks++) {
            #pragma unroll
            for (int np = 0; np < 4; np++) {
                unsigned b0, b1, b2, b3;
                LDSM4(b0, b1, b2, b3, kfa + np * 2304 + ks * 32);
                unsigned bb0[2] = {b0, b1}, bb1[2] = {b2, b3};
                mma16(sc[2*np],     qa[ks], bb0);
                mma16(sc[2*np + 1], qa[ks], bb1);
            }
        }

        // P = exp2(S) in f16x2
        unsigned pu[8][2];
        #pragma unroll
        for (int nt = 0; nt < 8; nt++) {
            pu[nt][0] = ex2_f16x2(pack_f16(sc[nt][0], sc[nt][1]));
            pu[nt][1] = ex2_f16x2(pack_f16(sc[nt][2], sc[nt][3]));
        }

        // l row-sums on the fma pipe: HADD2 tree over the 8 packed fragments
        {
            unsigned t00 = hadd2u(pu[0][0], pu[1][0]);
            unsigned t01 = hadd2u(pu[2][0], pu[3][0]);
            unsigned t02 = hadd2u(pu[4][0], pu[5][0]);
            unsigned t03 = hadd2u(pu[6][0], pu[7][0]);
            unsigned t0s = hadd2u(hadd2u(t00, t01), hadd2u(t02, t03));
            float2 f0 = __half22float2(*(__half2*)&t0s);
            l0 += f0.x + f0.y;
            unsigned t10 = hadd2u(pu[0][1], pu[1][1]);
            unsigned t11 = hadd2u(pu[2][1], pu[3][1]);
            unsigned t12 = hadd2u(pu[4][1], pu[5][1]);
            unsigned t13 = hadd2u(pu[6][1], pu[7][1]);
            unsigned t1s = hadd2u(hadd2u(t10, t11), hadd2u(t12, t13));
            float2 f1 = __half22float2(*(__half2*)&t1s);
            l1 += f1.x + f1.y;
        }

        // O += P V^T
        #pragma unroll
        for (int ks = 0; ks < 4; ks++) {
            unsigned pa[4] = { pu[2*ks][0], pu[2*ks][1],
                               pu[2*ks+1][0], pu[2*ks+1][1] };
            #pragma unroll
            for (int np = 0; np < 4; np++) {
                unsigned b0, b1, b2, b3;
                LDSM4(b0, b1, b2, b3, vfa + np * 2304 + ks * 32);
                unsigned bb0[2] = {b0, b1}, bb1[2] = {b2, b3};
                mma16h(o[2*np],     pa, bb0);
                mma16h(o[2*np + 1], pa, bb1);
            }
        }
    }

    // quad-reduce l (each thread holds 16 of 64 columns per row)
    l0 += __shfl_xor_sync(0xffffffffu, l0, 1);
    l0 += __shfl_xor_sync(0xffffffffu, l0, 2);
    l1 += __shfl_xor_sync(0xffffffffu, l1, 1);
    l1 += __shfl_xor_sync(0xffffffffu, l1, 2);

    float il0 = 1.f / l0, il1 = 1.f / l1;
    unsigned* hb = hout + ((size_t)bz << 10) * 256 + hh * 32;
    size_t tr0 = (size_t)(t0 + w * 16 + g) * 256;
    size_t tr1 = (size_t)(t0 + w * 16 + g + 8) * 256;
    #pragma unroll
    for (int nt = 0; nt < 8; nt++) {
        hb[tr0 + 4 * nt + tig] = pack_bf16(o[nt][0] * il0, o[nt][1] * il0);
        hb[tr1 + 4 * nt + tig] = pack_bf16(o[nt][2] * il1, o[nt][3] * il1);
    }
}

// ---------------------------------------------------------------------------
extern "C" void kernel_launch(void* const* d_in, const int* in_sizes, int n_in,
                              void* d_out, int out_size)
{
    const float* x      = (const float*)d_in[0];
    const float* gamma  = (const float*)d_in[1];
    const float* beta   = (const float*)d_in[2];
    const float* w_qkv  = (const float*)d_in[3];
    const float* b_qkv  = (const float*)d_in[4];
    const float* w_proj = (const float*)d_in[5];
    const float* b_proj = (const float*)d_in[6];

    void *p_xn, *p_qk, *p_v, *p_h, *p_wq, *p_wp;
    cudaGetSymbolAddress(&p_xn, g_xn);
    cudaGetSymbolAddress(&p_qk, g_qk);
    cudaGetSymbolAddress(&p_v,  g_v);
    cudaGetSymbolAddress(&p_h,  g_h);
    cudaGetSymbolAddress(&p_wq, g_wq);
    cudaGetSymbolAddress(&p_wp, g_wp);

    const int gn_smem   = 16 * 1024 * 4;              // 64 KB
    const int gemm_smem = 2 * 3 * 2560 * 4;           // 61440 B (BK=32, 3 stages)
    const int attn_smem = (4608 + 2 * 4 * 2304) * 4;  // 92160 B (4 stages, 64 kv)
    cudaFuncSetAttribute(groupnorm_t, cudaFuncAttributeMaxDynamicSharedMemorySize, gn_smem);
    cudaFuncSetAttribute(gemm2<0>, cudaFuncAttributeMaxDynamicSharedMemorySize, gemm_smem);
    cudaFuncSetAttribute(gemm2<1>, cudaFuncAttributeMaxDynamicSharedMemorySize, gemm_smem);
    cudaFuncSetAttribute(attn2, cudaFuncAttributeMaxDynamicSharedMemorySize, attn_smem);

    wconvert2<<<2048, 256>>>(w_qkv, w_proj, (unsigned*)p_wq, (unsigned*)p_wp);
    groupnorm_t<<<B_ * GROUPS, 256, gn_smem>>>(x, gamma, beta, (unsigned*)p_xn);

    gemm2<0><<<dim3(12, 8, B_), 256, gemm_smem>>>(
        (const unsigned*)p_wq, (const unsigned*)p_xn, b_qkv, nullptr,
        p_qk, (unsigned*)p_v);

    attn2<<<dim3(8, B_ * 8), 256, attn_smem>>>(
        (const unsigned*)p_qk, (const unsigned*)p_v, (unsigned*)p_h);

    gemm2<1><<<dim3(4, 8, B_), 256, gemm_smem>>>(
        (const unsigned*)p_wp, (const unsigned*)p_h, b_proj, x,
        d_out, nullptr);
}